// round 9
// baseline (speedup 1.0000x reference)
#include <cuda_runtime.h>
#include <cstdint>

#define Dn  200
#define Cn  8
#define Gn  10000
#define Vn  20000
#define VGn 50000
#define GLn 500
#define EPSf 1e-8f
#define LN2f 0.6931471805599453f

// Scratch (no allocations allowed)
__device__ __align__(16) uint8_t g_gen8[Dn * Vn];       // genotypes u8 [d][v]
__device__ __align__(16) uint8_t g_obsT[Cn * GLn * Dn]; // obs u8 TRANSPOSED [c][lg][d]
__device__ __align__(16) uint8_t g_gsel[Dn * VGn];      // genotypes[:, sel[vg]] [d][vg]
__device__ __align__(16) uint32_t g_gpack[13 * VGn];    // 2-bit packed gsel: [d/16][vg]
__device__ float    g_libx[Cn * Dn];                    // [c][d] lib
__device__ float    g_liby[Cn * Dn];                    // [c][d] log(lib)

// classification state (zero-initialized at load; atomicMax idempotent across replays)
__device__ int g_max3[3];
__device__ const int* g_p_vg2g;
__device__ const int* g_p_sel;
__device__ const int* g_p_vg2lg;

// ---------------------------------------------------------------------------
__global__ void classify_kernel(const int* __restrict__ a,
                                const int* __restrict__ b,
                                const int* __restrict__ c) {
    __shared__ int sred[256];
    const int tid = threadIdx.x;
    const int* arrs[3] = {a, b, c};
    for (int j = 0; j < 3; j++) {
        int m = 0;
        for (int i = blockIdx.x * 256 + tid; i < VGn; i += gridDim.x * 256)
            m = max(m, arrs[j][i]);
        sred[tid] = m;
        __syncthreads();
        for (int s = 128; s > 0; s >>= 1) {
            if (tid < s) sred[tid] = max(sred[tid], sred[tid + s]);
            __syncthreads();
        }
        if (tid == 0) atomicMax(&g_max3[j], sred[0]);
        __syncthreads();
    }
}

__global__ void resolve_kernel(const int* a, const int* b, const int* c) {
    const int* arrs[3] = {a, b, c};
    for (int j = 0; j < 3; j++) {
        const int m = g_max3[j];
        if (m < GLn)      g_p_vg2lg = arrs[j];
        else if (m < Gn)  g_p_vg2g  = arrs[j];
        else              g_p_sel   = arrs[j];
    }
}

// ---------------------------------------------------------------------------
__global__ void prep_kernel(const float* __restrict__ genotypes,
                            const float* __restrict__ obs,
                            const float* __restrict__ lib) {
    const int q = blockIdx.x * blockDim.x + threadIdx.x;
    if (q < Dn * Vn / 4) {
        const float4 g4 = ((const float4*)genotypes)[q];
        uint32_t w = (uint32_t)__float2int_rn(g4.x)
                   | ((uint32_t)__float2int_rn(g4.y) << 8)
                   | ((uint32_t)__float2int_rn(g4.z) << 16)
                   | ((uint32_t)__float2int_rn(g4.w) << 24);
        ((uint32_t*)g_gen8)[q] = w;
    }
    if (q < Dn * Cn * GLn / 4) {
        const float4 o4 = ((const float4*)obs)[q];
        const int i = q * 4;                    // flat [d][c][lg], GLn%4==0
        const int d  = i / (Cn * GLn);
        const int r  = i - d * (Cn * GLn);
        const int c  = r / GLn;
        const int lg = r - c * GLn;
        uint8_t* base = g_obsT + d;
        base[(c * GLn + lg + 0) * Dn] = (uint8_t)__float2int_rn(o4.x);
        base[(c * GLn + lg + 1) * Dn] = (uint8_t)__float2int_rn(o4.y);
        base[(c * GLn + lg + 2) * Dn] = (uint8_t)__float2int_rn(o4.z);
        base[(c * GLn + lg + 3) * Dn] = (uint8_t)__float2int_rn(o4.w);
    }
    if (q < Dn * Cn) {
        const int d = q / Cn;
        const int c = q - d * Cn;
        const float lv = lib[q];
        g_libx[c * Dn + d] = lv;
        g_liby[c * Dn + d] = logf(lv);
    }
}

// ---------------------------------------------------------------------------
// Gather genotypes[d, sel[vg]] -> g_gsel[d, vg]. TWO rows per block so the
// grid (100) fits one wave on 148 SMs; sel loads amortized over both rows.
// ---------------------------------------------------------------------------
__global__ __launch_bounds__(1024) void gsel_kernel() {
    __shared__ uint32_t row32[2][Vn / 4];   // 40 KB static
    const int* sel = g_p_sel;
    const int d0 = blockIdx.x * 2;
    for (int j = threadIdx.x; j < Vn / 4; j += 1024) {
        row32[0][j] = ((const uint32_t*)(g_gen8 + d0 * Vn))[j];
        row32[1][j] = ((const uint32_t*)(g_gen8 + (d0 + 1) * Vn))[j];
    }
    __syncthreads();
    const uint8_t* r0 = (const uint8_t*)row32[0];
    const uint8_t* r1 = (const uint8_t*)row32[1];
    uint32_t* dst0 = (uint32_t*)(g_gsel + d0 * VGn);
    uint32_t* dst1 = (uint32_t*)(g_gsel + (d0 + 1) * VGn);
    for (int q = threadIdx.x; q < VGn / 4; q += 1024) {
        const int4 s4 = ((const int4*)sel)[q];
        dst0[q] = (uint32_t)r0[s4.x]
                | ((uint32_t)r0[s4.y] << 8)
                | ((uint32_t)r0[s4.z] << 16)
                | ((uint32_t)r0[s4.w] << 24);
        dst1[q] = (uint32_t)r1[s4.x]
                | ((uint32_t)r1[s4.y] << 8)
                | ((uint32_t)r1[s4.z] << 16)
                | ((uint32_t)r1[s4.w] << 24);
    }
}

// ---------------------------------------------------------------------------
__global__ void pack_kernel() {
    const int q = blockIdx.x * 256 + threadIdx.x;   // vg quad
    if (q >= VGn / 4) return;
    for (int t = 0; t < 13; t++) {
        uint32_t p0 = 0, p1 = 0, p2 = 0, p3 = 0;
        const int dmax = (t == 12) ? 8 : 16;
#pragma unroll
        for (int k = 0; k < 16; k++) {
            if (k < dmax) {
                const uint32_t w = ((const uint32_t*)(g_gsel + (t * 16 + k) * VGn))[q];
                p0 |= ((w >> 0)  & 3u) << (2 * k);
                p1 |= ((w >> 8)  & 3u) << (2 * k);
                p2 |= ((w >> 16) & 3u) << (2 * k);
                p3 |= ((w >> 24) & 3u) << (2 * k);
            }
        }
        uint32_t* dst = g_gpack + t * VGn + q * 4;
        dst[0] = p0; dst[1] = p1; dst[2] = p2; dst[3] = p3;
    }
}

// ---------------------------------------------------------------------------
// Main kernel — QUARTER-resolution per-thread table for high occupancy.
//   T[j] = lgamma(1+4j) - cum[4j],  cum[n] = sum_{k<n} ln(tc+k)
//   v = 4j+m:  F[v] = T[j] + ln(prod_{i<m}(vf-i)) - ln(prod_{i<m}(tcv-i)),
//   tcv = tc+vf-1.  (m=0 -> both products 1 -> fixup 0; verified v=0..5.)
//   elbo = (tc*ln2 + v*ln2)*log2(1+r) - v*(Q0 + g*fc + log lib) + F[v]
// ---------------------------------------------------------------------------
#define TPB 128
#define FQ  27   // stride 27: gcd(27,32)=1 -> bank spread

__global__ __launch_bounds__(TPB, 12) void main_kernel(
    const float* __restrict__ fc_log,
    const float* __restrict__ baseline_log,
    const float* __restrict__ dispersion_log,
    float*       __restrict__ out) {
    __shared__ float LF4[25];          // lgamma(1+4j)
    __shared__ float Fq[TPB * FQ];     // 13.8 KB
    __shared__ float slibx[Dn];
    __shared__ float sliby[Dn];

    const int tid = threadIdx.x;
    const int c   = blockIdx.y;
    const int vg  = blockIdx.x * TPB + tid;
    const bool active = (vg < VGn);
    const int vgs = active ? vg : 0;

    if (tid < 25) LF4[tid] = lgammaf((float)(4 * tid + 1));
    for (int n = tid; n < Dn; n += TPB) {
        slibx[n] = g_libx[c * Dn + n];
        sliby[n] = g_liby[c * Dn + n];
    }

    // Per-(c,vg) parameters
    float tc = 1.f, eE = 0.f, R0 = 0.f, R1 = 0.f, R2 = 0.f;
    float Q0 = 0.f, fc = 0.f, tcln2 = 0.f;
    int lg = 0;
    {
        const int gix = g_p_vg2g[vgs];
        lg = g_p_vg2lg[vgs];
        fc = fc_log[c * VGn + vgs];
        const float b  = baseline_log[c * Gn + gix];
        const float dl = dispersion_log[c * Gn + gix];
        const float disp = fminf(expf(dl), 20.0f);
        tc = 1.0f / disp;
        tcln2 = tc * LN2f;
        const float itc = 1.0f / (tc + EPSf);
        const float ltc = logf(tc + EPSf);
        eE = EPSf * itc;
        const float e0 = expf(b);
        const float ef = expf(fc);
        R0 = e0 * itc; R1 = R0 * ef; R2 = R1 * ef;
        Q0 = b - ltc;
    }
    __syncthreads();  // LF4 + slib ready

    // Build per-thread quarter table: 25 steps of log-of-4-term-product.
    float* Ft = Fq + tid * FQ;
    {
        float cum = 0.f, x = tc;
#pragma unroll 5
        for (int j = 0; j < 25; j++) {
            Ft[j] = LF4[j] - cum;
            const float p = (x * (x + 1.0f)) * ((x + 2.0f) * (x + 3.0f));
            cum += __logf(p);   // product <= ~1e8, fits fp32; err ~2e-6/step
            x += 4.0f;
        }
    }

    const uint32_t* gpackp = g_gpack + vgs;
    const uint2*    obsp   = (const uint2*)(g_obsT + (c * GLn + lg) * Dn);
    float* outp = out + c * VGn + vg;

#define BODY(k, w, dk)                                                        \
    {                                                                         \
        const int v  = __byte_perm((w), 0, 0x4440 | ((k) & 3));               \
        const int m  = v & 3;                                                 \
        const int gv = (pack >> (2 * (k))) & 3;                               \
        const float vf = (float)v;                                            \
        const float gf = (float)gv;                                           \
        const float R = (gv == 0) ? R0 : ((gv == 1) ? R1 : R2);               \
        const float r = fmaf(R, slibx[(dk)], eE);                             \
        const float l2 = __log2f(1.0f + r);                                   \
        const float A = fmaf(vf, LN2f, tcln2);                                \
        const float tcv = tc + vf - 1.0f;                                     \
        const float n0 = (m > 0) ? vf : 1.0f;                                 \
        const float d0_ = (m > 0) ? tcv : 1.0f;                               \
        const float n1 = (m > 1) ? vf - 1.0f : 1.0f;                          \
        const float d1_ = (m > 1) ? tcv - 1.0f : 1.0f;                        \
        const float n2 = (m > 2) ? vf - 2.0f : 1.0f;                          \
        const float d2_ = (m > 2) ? tcv - 2.0f : 1.0f;                        \
        const float num = (n0 * n1) * n2;                                     \
        const float den = (d0_ * d1_) * d2_;                                  \
        float fv = Ft[v >> 2];                                                \
        fv = fmaf(LN2f, __log2f(num) - __log2f(den), fv);                     \
        const float q = fmaf(gf, fc, Q0) + sliby[(dk)];                       \
        float res = fmaf(-vf, q, fv);                                         \
        res = fmaf(A, l2, res);                                               \
        if (active) __stcs(op + (k) * (Cn * VGn), res);                       \
    }

    for (int t = 0; t < 12; t++) {
        const uint32_t pack = gpackp[t * VGn];
        const uint2 a = obsp[2 * t];
        const uint2 b = obsp[2 * t + 1];
        float* op = outp + t * 16 * (Cn * VGn);
#pragma unroll
        for (int k = 0; k < 16; k++) {
            const uint32_t w = (k < 8) ? ((k < 4) ? a.x : a.y)
                                       : ((k < 12) ? b.x : b.y);
            BODY(k, w, t * 16 + k)
        }
    }
    {   // tail: d = 192..199
        const uint32_t pack = gpackp[12 * VGn];
        const uint2 a = obsp[24];
        float* op = outp + 192 * (Cn * VGn);
#pragma unroll
        for (int k = 0; k < 8; k++) {
            const uint32_t w = (k < 4) ? a.x : a.y;
            BODY(k, w, 192 + k)
        }
    }
#undef BODY
}

// ---------------------------------------------------------------------------
extern "C" void kernel_launch(void* const* d_in, const int* in_sizes, int n_in,
                              void* d_out, int out_size) {
    const float* genotypes = nullptr;
    const float* obs       = nullptr;
    const float* fc_log    = nullptr;
    const float* lib       = nullptr;
    const float* cg[2]     = {nullptr, nullptr};
    const int*   vgarr[3]  = {nullptr, nullptr, nullptr};
    int n_cg = 0, n_vg = 0;

    for (int i = 0; i < n_in; i++) {
        switch (in_sizes[i]) {
            case Dn * Vn:        genotypes = (const float*)d_in[i]; break;
            case Dn * Cn * GLn:  obs       = (const float*)d_in[i]; break;
            case Cn * VGn:       fc_log    = (const float*)d_in[i]; break;
            case Dn * Cn:        lib       = (const float*)d_in[i]; break;
            case Cn * Gn:        if (n_cg < 2) cg[n_cg++] = (const float*)d_in[i]; break;
            case VGn:            if (n_vg < 3) vgarr[n_vg++] = (const int*)d_in[i]; break;
            default: break;
        }
    }
    const float* baseline_log   = cg[0];
    const float* dispersion_log = cg[1];
    float* out = (float*)d_out;

    classify_kernel<<<64, 256>>>(vgarr[0], vgarr[1], vgarr[2]);
    resolve_kernel<<<1, 1>>>(vgarr[0], vgarr[1], vgarr[2]);
    prep_kernel<<<(Dn * Vn / 4 + 255) / 256, 256>>>(genotypes, obs, lib);
    gsel_kernel<<<Dn / 2, 1024>>>();
    pack_kernel<<<(VGn / 4 + 255) / 256, 256>>>();

    dim3 grid((VGn + TPB - 1) / TPB, Cn);
    main_kernel<<<grid, TPB>>>(fc_log, baseline_log, dispersion_log, out);
}

// round 10
// speedup vs baseline: 1.0820x; 1.0820x over previous
#include <cuda_runtime.h>
#include <cstdint>

#define Dn  200
#define Cn  8
#define Gn  10000
#define Vn  20000
#define VGn 50000
#define GLn 500
#define EPSf 1e-8f
#define LN2f 0.6931471805599453f

// Scratch (no allocations allowed)
__device__ __align__(16) uint8_t g_gen8[Dn * Vn];       // genotypes u8 [d][v]
__device__ __align__(16) uint8_t g_obsT[Cn * GLn * Dn]; // obs u8 TRANSPOSED [c][lg][d]
__device__ __align__(16) uint8_t g_gsel[Dn * VGn];      // genotypes[:, sel[vg]] [d][vg]
__device__ __align__(16) uint32_t g_gpack[13 * VGn];    // 2-bit packed gsel: [d/16][vg]
__device__ float    g_libx[Cn * Dn];                    // [c][d] lib
__device__ float    g_liby[Cn * Dn];                    // [c][d] log(lib)

// classification state (zero-initialized at load; atomicMax idempotent across replays)
__device__ int g_max3[3];
__device__ const int* g_p_vg2g;
__device__ const int* g_p_sel;
__device__ const int* g_p_vg2lg;

// ---------------------------------------------------------------------------
__global__ void classify_kernel(const int* __restrict__ a,
                                const int* __restrict__ b,
                                const int* __restrict__ c) {
    __shared__ int sred[256];
    const int tid = threadIdx.x;
    const int* arrs[3] = {a, b, c};
    for (int j = 0; j < 3; j++) {
        int m = 0;
        for (int i = blockIdx.x * 256 + tid; i < VGn; i += gridDim.x * 256)
            m = max(m, arrs[j][i]);
        sred[tid] = m;
        __syncthreads();
        for (int s = 128; s > 0; s >>= 1) {
            if (tid < s) sred[tid] = max(sred[tid], sred[tid + s]);
            __syncthreads();
        }
        if (tid == 0) atomicMax(&g_max3[j], sred[0]);
        __syncthreads();
    }
}

__global__ void resolve_kernel(const int* a, const int* b, const int* c) {
    const int* arrs[3] = {a, b, c};
    for (int j = 0; j < 3; j++) {
        const int m = g_max3[j];
        if (m < GLn)      g_p_vg2lg = arrs[j];
        else if (m < Gn)  g_p_vg2g  = arrs[j];
        else              g_p_sel   = arrs[j];
    }
}

// ---------------------------------------------------------------------------
__global__ void prep_kernel(const float* __restrict__ genotypes,
                            const float* __restrict__ obs,
                            const float* __restrict__ lib) {
    const int q = blockIdx.x * blockDim.x + threadIdx.x;
    if (q < Dn * Vn / 4) {
        const float4 g4 = ((const float4*)genotypes)[q];
        uint32_t w = (uint32_t)__float2int_rn(g4.x)
                   | ((uint32_t)__float2int_rn(g4.y) << 8)
                   | ((uint32_t)__float2int_rn(g4.z) << 16)
                   | ((uint32_t)__float2int_rn(g4.w) << 24);
        ((uint32_t*)g_gen8)[q] = w;
    }
    if (q < Dn * Cn * GLn / 4) {
        const float4 o4 = ((const float4*)obs)[q];
        const int i = q * 4;                    // flat [d][c][lg], GLn%4==0
        const int d  = i / (Cn * GLn);
        const int r  = i - d * (Cn * GLn);
        const int c  = r / GLn;
        const int lg = r - c * GLn;
        uint8_t* base = g_obsT + d;
        base[(c * GLn + lg + 0) * Dn] = (uint8_t)__float2int_rn(o4.x);
        base[(c * GLn + lg + 1) * Dn] = (uint8_t)__float2int_rn(o4.y);
        base[(c * GLn + lg + 2) * Dn] = (uint8_t)__float2int_rn(o4.z);
        base[(c * GLn + lg + 3) * Dn] = (uint8_t)__float2int_rn(o4.w);
    }
    if (q < Dn * Cn) {
        const int d = q / Cn;
        const int c = q - d * Cn;
        const float lv = lib[q];
        g_libx[c * Dn + d] = lv;
        g_liby[c * Dn + d] = logf(lv);
    }
}

// ---------------------------------------------------------------------------
// Gather genotypes[d, sel[vg]] -> g_gsel[d, vg] (shared-staged row, 32 warps).
// ---------------------------------------------------------------------------
__global__ __launch_bounds__(1024) void gsel_kernel() {
    __shared__ uint32_t row32[Vn / 4];
    const int* sel = g_p_sel;
    const int d = blockIdx.x;
    const uint32_t* src = (const uint32_t*)(g_gen8 + d * Vn);
    for (int j = threadIdx.x; j < Vn / 4; j += 1024) row32[j] = src[j];
    __syncthreads();
    const uint8_t* row = (const uint8_t*)row32;
    uint32_t* dst = (uint32_t*)(g_gsel + d * VGn);
    for (int q = threadIdx.x; q < VGn / 4; q += 1024) {
        const int4 s4 = ((const int4*)sel)[q];
        uint32_t w = (uint32_t)row[s4.x]
                   | ((uint32_t)row[s4.y] << 8)
                   | ((uint32_t)row[s4.z] << 16)
                   | ((uint32_t)row[s4.w] << 24);
        dst[q] = w;
    }
}

// ---------------------------------------------------------------------------
__global__ void pack_kernel() {
    const int q = blockIdx.x * 256 + threadIdx.x;   // vg quad
    if (q >= VGn / 4) return;
    for (int t = 0; t < 13; t++) {
        uint32_t p0 = 0, p1 = 0, p2 = 0, p3 = 0;
        const int dmax = (t == 12) ? 8 : 16;
#pragma unroll
        for (int k = 0; k < 16; k++) {
            if (k < dmax) {
                const uint32_t w = ((const uint32_t*)(g_gsel + (t * 16 + k) * VGn))[q];
                p0 |= ((w >> 0)  & 3u) << (2 * k);
                p1 |= ((w >> 8)  & 3u) << (2 * k);
                p2 |= ((w >> 16) & 3u) << (2 * k);
                p3 |= ((w >> 24) & 3u) << (2 * k);
            }
        }
        uint32_t* dst = g_gpack + t * VGn + q * 4;
        dst[0] = p0; dst[1] = p1; dst[2] = p2; dst[3] = p3;
    }
}

// ---------------------------------------------------------------------------
// Main kernel (R8 math, TRANSPOSED table layout -> conflict-free LDS).
// Table: Fh[j * TPB + tid], j = v>>1. Bank = (j*128 + tid) % 32 = lane id,
// so random per-lane j never conflicts. Build writes likewise conflict-free.
// Half table: Fh[j] = lgamma(1+2j) - cum[2j];
// odd v: F[v] = Fh[v>>1] + ln2*(log2(v) - log2(tc+v-1)).
//   elbo = (tc*ln2 + v*ln2)*log2(1+r) - v*(Q0 + g*fc + log lib) + F[v]
// ---------------------------------------------------------------------------
#define TPB 128
#define NH  50   // half-table entries

__global__ __launch_bounds__(TPB) void main_kernel(
    const float* __restrict__ fc_log,
    const float* __restrict__ baseline_log,
    const float* __restrict__ dispersion_log,
    float*       __restrict__ out) {
    __shared__ float LF[100];
    __shared__ float Fh[NH * TPB];     // transposed: [j][tid], 25.6 KB
    __shared__ float slibx[Dn];
    __shared__ float sliby[Dn];

    const int tid = threadIdx.x;
    const int c   = blockIdx.y;
    const int vg  = blockIdx.x * TPB + tid;
    const bool active = (vg < VGn);
    const int vgs = active ? vg : 0;

    for (int n = tid; n < 100; n += TPB) LF[n] = lgammaf((float)(n + 1));
    for (int n = tid; n < Dn;  n += TPB) {
        slibx[n] = g_libx[c * Dn + n];
        sliby[n] = g_liby[c * Dn + n];
    }

    // Per-(c,vg) parameters
    float tc = 1.f, eE = 0.f, R0 = 0.f, R1 = 0.f, R2 = 0.f;
    float Q0 = 0.f, fc = 0.f, tcln2 = 0.f;
    int lg = 0;
    {
        const int gix = g_p_vg2g[vgs];
        lg = g_p_vg2lg[vgs];
        fc = fc_log[c * VGn + vgs];
        const float b  = baseline_log[c * Gn + gix];
        const float dl = dispersion_log[c * Gn + gix];
        const float disp = fminf(expf(dl), 20.0f);
        tc = 1.0f / disp;
        tcln2 = tc * LN2f;
        const float itc = 1.0f / (tc + EPSf);
        const float ltc = logf(tc + EPSf);
        eE = EPSf * itc;
        const float e0 = expf(b);
        const float ef = expf(fc);
        R0 = e0 * itc; R1 = R0 * ef; R2 = R1 * ef;
        Q0 = b - ltc;
    }
    __syncthreads();  // LF + slib ready

    // Build per-thread half table (transposed writes, conflict-free)
    float* Ft = Fh + tid;
    {
        float cum = 0.f, x = tc;
#pragma unroll 5
        for (int n = 0; n < 100; n += 2) {
            Ft[(n >> 1) * TPB] = LF[n] - cum;
            cum += __logf(x) + __logf(x + 1.0f);
            x += 2.0f;
        }
    }

    const uint32_t* gpackp = g_gpack + vgs;
    const uint2*    obsp   = (const uint2*)(g_obsT + (c * GLn + lg) * Dn);
    float* outp = out + c * VGn + vg;

#define BODY(k, w, dk)                                                        \
    {                                                                         \
        const int v  = __byte_perm((w), 0, 0x4440 | ((k) & 3));               \
        const int gv = (pack >> (2 * (k))) & 3;                               \
        const float vf = (float)v;                                            \
        const float gf = (float)gv;                                           \
        const float R = (gv == 0) ? R0 : ((gv == 1) ? R1 : R2);               \
        const float r = fmaf(R, slibx[(dk)], eE);                             \
        const float l2 = __log2f(1.0f + r);                                   \
        const float A = fmaf(vf, LN2f, tcln2);                                \
        float fv = Ft[(v >> 1) * TPB];                                        \
        if (v & 1) fv += LN2f * (__log2f(vf) - __log2f(tc + vf - 1.0f));      \
        const float q = fmaf(gf, fc, Q0) + sliby[(dk)];                       \
        float res = fmaf(-vf, q, fv);                                         \
        res = fmaf(A, l2, res);                                               \
        if (active) __stcs(op + (k) * (Cn * VGn), res);                       \
    }

    for (int t = 0; t < 12; t++) {
        const uint32_t pack = gpackp[t * VGn];
        const uint2 a = obsp[2 * t];
        const uint2 b = obsp[2 * t + 1];
        float* op = outp + t * 16 * (Cn * VGn);
#pragma unroll
        for (int k = 0; k < 16; k++) {
            const uint32_t w = (k < 8) ? ((k < 4) ? a.x : a.y)
                                       : ((k < 12) ? b.x : b.y);
            BODY(k, w, t * 16 + k)
        }
    }
    {   // tail: d = 192..199
        const uint32_t pack = gpackp[12 * VGn];
        const uint2 a = obsp[24];
        float* op = outp + 192 * (Cn * VGn);
#pragma unroll
        for (int k = 0; k < 8; k++) {
            const uint32_t w = (k < 4) ? a.x : a.y;
            BODY(k, w, 192 + k)
        }
    }
#undef BODY
}

// ---------------------------------------------------------------------------
extern "C" void kernel_launch(void* const* d_in, const int* in_sizes, int n_in,
                              void* d_out, int out_size) {
    const float* genotypes = nullptr;
    const float* obs       = nullptr;
    const float* fc_log    = nullptr;
    const float* lib       = nullptr;
    const float* cg[2]     = {nullptr, nullptr};
    const int*   vgarr[3]  = {nullptr, nullptr, nullptr};
    int n_cg = 0, n_vg = 0;

    for (int i = 0; i < n_in; i++) {
        switch (in_sizes[i]) {
            case Dn * Vn:        genotypes = (const float*)d_in[i]; break;
            case Dn * Cn * GLn:  obs       = (const float*)d_in[i]; break;
            case Cn * VGn:       fc_log    = (const float*)d_in[i]; break;
            case Dn * Cn:        lib       = (const float*)d_in[i]; break;
            case Cn * Gn:        if (n_cg < 2) cg[n_cg++] = (const float*)d_in[i]; break;
            case VGn:            if (n_vg < 3) vgarr[n_vg++] = (const int*)d_in[i]; break;
            default: break;
        }
    }
    const float* baseline_log   = cg[0];
    const float* dispersion_log = cg[1];
    float* out = (float*)d_out;

    classify_kernel<<<64, 256>>>(vgarr[0], vgarr[1], vgarr[2]);
    resolve_kernel<<<1, 1>>>(vgarr[0], vgarr[1], vgarr[2]);
    prep_kernel<<<(Dn * Vn / 4 + 255) / 256, 256>>>(genotypes, obs, lib);
    gsel_kernel<<<Dn, 1024>>>();
    pack_kernel<<<(VGn / 4 + 255) / 256, 256>>>();

    dim3 grid((VGn + TPB - 1) / TPB, Cn);
    main_kernel<<<grid, TPB>>>(fc_log, baseline_log, dispersion_log, out);
}

// round 13
// speedup vs baseline: 1.1092x; 1.0251x over previous
#include <cuda_runtime.h>
#include <cstdint>

#define Dn  200
#define Cn  8
#define Gn  10000
#define Vn  20000
#define VGn 50000
#define GLn 500
#define EPSf 1e-8f
#define LN2f 0.6931471805599453f

// Scratch (no allocations allowed)
__device__ __align__(16) uint8_t g_gen8[Dn * Vn];       // genotypes u8 [d][v]
__device__ __align__(16) uint8_t g_obsT[Cn * GLn * Dn]; // obs u8 TRANSPOSED [c][lg][d]
__device__ __align__(16) uint8_t g_gsel[Dn * VGn];      // genotypes[:, sel[vg]] [d][vg]
__device__ __align__(16) uint32_t g_gpack[13 * VGn];    // 2-bit packed gsel: [d/16][vg]
__device__ float2   g_lib2[Cn * Dn];                    // [c][d] = {lib, log(lib)/256}

// classification state (zero-initialized at load; atomicMax idempotent across replays)
__device__ int g_max3[3];
__device__ const int* g_p_vg2g;
__device__ const int* g_p_sel;
__device__ const int* g_p_vg2lg;

// ---------------------------------------------------------------------------
__global__ void classify_kernel(const int* __restrict__ a,
                                const int* __restrict__ b,
                                const int* __restrict__ c) {
    __shared__ int sred[256];
    const int tid = threadIdx.x;
    const int* arrs[3] = {a, b, c};
    for (int j = 0; j < 3; j++) {
        int m = 0;
        for (int i = blockIdx.x * 256 + tid; i < VGn; i += gridDim.x * 256)
            m = max(m, arrs[j][i]);
        sred[tid] = m;
        __syncthreads();
        for (int s = 128; s > 0; s >>= 1) {
            if (tid < s) sred[tid] = max(sred[tid], sred[tid + s]);
            __syncthreads();
        }
        if (tid == 0) atomicMax(&g_max3[j], sred[0]);
        __syncthreads();
    }
}

__global__ void resolve_kernel(const int* a, const int* b, const int* c) {
    const int* arrs[3] = {a, b, c};
    for (int j = 0; j < 3; j++) {
        const int m = g_max3[j];
        if (m < GLn)      g_p_vg2lg = arrs[j];
        else if (m < Gn)  g_p_vg2g  = arrs[j];
        else              g_p_sel   = arrs[j];
    }
}

// ---------------------------------------------------------------------------
__global__ void prep_kernel(const float* __restrict__ genotypes,
                            const float* __restrict__ obs,
                            const float* __restrict__ lib) {
    const int q = blockIdx.x * blockDim.x + threadIdx.x;
    if (q < Dn * Vn / 4) {
        const float4 g4 = ((const float4*)genotypes)[q];
        uint32_t w = (uint32_t)__float2int_rn(g4.x)
                   | ((uint32_t)__float2int_rn(g4.y) << 8)
                   | ((uint32_t)__float2int_rn(g4.z) << 16)
                   | ((uint32_t)__float2int_rn(g4.w) << 24);
        ((uint32_t*)g_gen8)[q] = w;
    }
    if (q < Dn * Cn * GLn / 4) {
        const float4 o4 = ((const float4*)obs)[q];
        const int i = q * 4;                    // flat [d][c][lg], GLn%4==0
        const int d  = i / (Cn * GLn);
        const int r  = i - d * (Cn * GLn);
        const int c  = r / GLn;
        const int lg = r - c * GLn;
        uint8_t* base = g_obsT + d;
        base[(c * GLn + lg + 0) * Dn] = (uint8_t)__float2int_rn(o4.x);
        base[(c * GLn + lg + 1) * Dn] = (uint8_t)__float2int_rn(o4.y);
        base[(c * GLn + lg + 2) * Dn] = (uint8_t)__float2int_rn(o4.z);
        base[(c * GLn + lg + 3) * Dn] = (uint8_t)__float2int_rn(o4.w);
    }
    if (q < Dn * Cn) {
        const int d = q / Cn;
        const int c = q - d * Cn;
        const float lv = lib[q];
        // y = log(lib)/256 (exact power-of-2 scale, folded into main math)
        g_lib2[c * Dn + d] = make_float2(lv, logf(lv) * (1.0f / 256.0f));
    }
}

// ---------------------------------------------------------------------------
// Gather genotypes[d, sel[vg]] -> g_gsel[d, vg] (shared-staged row, 32 warps).
// ---------------------------------------------------------------------------
__global__ __launch_bounds__(1024) void gsel_kernel() {
    __shared__ uint32_t row32[Vn / 4];
    const int* sel = g_p_sel;
    const int d = blockIdx.x;
    const uint32_t* src = (const uint32_t*)(g_gen8 + d * Vn);
    for (int j = threadIdx.x; j < Vn / 4; j += 1024) row32[j] = src[j];
    __syncthreads();
    const uint8_t* row = (const uint8_t*)row32;
    uint32_t* dst = (uint32_t*)(g_gsel + d * VGn);
    for (int q = threadIdx.x; q < VGn / 4; q += 1024) {
        const int4 s4 = ((const int4*)sel)[q];
        uint32_t w = (uint32_t)row[s4.x]
                   | ((uint32_t)row[s4.y] << 8)
                   | ((uint32_t)row[s4.z] << 16)
                   | ((uint32_t)row[s4.w] << 24);
        dst[q] = w;
    }
}

// ---------------------------------------------------------------------------
__global__ void pack_kernel() {
    const int q = blockIdx.x * 256 + threadIdx.x;   // vg quad
    if (q >= VGn / 4) return;
    for (int t = 0; t < 13; t++) {
        uint32_t p0 = 0, p1 = 0, p2 = 0, p3 = 0;
        const int dmax = (t == 12) ? 8 : 16;
#pragma unroll
        for (int k = 0; k < 16; k++) {
            if (k < dmax) {
                const uint32_t w = ((const uint32_t*)(g_gsel + (t * 16 + k) * VGn))[q];
                p0 |= ((w >> 0)  & 3u) << (2 * k);
                p1 |= ((w >> 8)  & 3u) << (2 * k);
                p2 |= ((w >> 16) & 3u) << (2 * k);
                p3 |= ((w >> 24) & 3u) << (2 * k);
            }
        }
        uint32_t* dst = g_gpack + t * VGn + q * 4;
        dst[0] = p0; dst[1] = p1; dst[2] = p2; dst[3] = p3;
    }
}

// ---------------------------------------------------------------------------
// Main kernel — R8 math, instruction-trimmed:
//  * v8 = v<<8 extracted directly via PRMT; table byte-offset = v8 & ~0x100
//    (== (v>>1)*512 for the transposed layout Fh[j*TPB+tid]).
//  * vf256 = (float)v8 = 256*v; the 256 is folded EXACTLY into:
//      A   = fmaf(vf256, LN2/256, tc*LN2)
//      q   = Qsel/256 + log(lib)/256          (res = fmaf(-vf256, q, ...))
//      odd fixup: ln(v/(tc+v-1)) = LN2*(log2(vf256) - log2(vf256 + 256(tc-1)))
//  * Q selected from precomputed Q0s/Q1s/Q2s (no I2F(gf), no extra FMA).
//  * slib single float2 LDS.64 broadcast.
// ---------------------------------------------------------------------------
#define TPB 128
#define NH  50

__global__ __launch_bounds__(TPB) void main_kernel(
    const float* __restrict__ fc_log,
    const float* __restrict__ baseline_log,
    const float* __restrict__ dispersion_log,
    float*       __restrict__ out) {
    __shared__ float  LF[100];
    __shared__ float  Fh[NH * TPB];     // transposed: [j][tid], 25.6 KB
    __shared__ float2 slib[Dn];

    const int tid = threadIdx.x;
    const int c   = blockIdx.y;
    const int vg  = blockIdx.x * TPB + tid;
    const bool active = (vg < VGn);
    const int vgs = active ? vg : 0;

    for (int n = tid; n < 100; n += TPB) LF[n] = lgammaf((float)(n + 1));
    for (int n = tid; n < Dn;  n += TPB) slib[n] = g_lib2[c * Dn + n];

    // Per-(c,vg) parameters
    float tc = 1.f, eE = 0.f, R0 = 0.f, R1 = 0.f, R2 = 0.f;
    float Q0s = 0.f, Q1s = 0.f, Q2s = 0.f, tcln2 = 0.f, tcm = 0.f;
    int lg = 0;
    {
        const int gix = g_p_vg2g[vgs];
        lg = g_p_vg2lg[vgs];
        const float fc = fc_log[c * VGn + vgs];
        const float b  = baseline_log[c * Gn + gix];
        const float dl = dispersion_log[c * Gn + gix];
        const float disp = fminf(expf(dl), 20.0f);
        tc = 1.0f / disp;
        tcln2 = tc * LN2f;
        tcm   = 256.0f * tc - 256.0f;          // 256*(tc-1)
        const float itc = 1.0f / (tc + EPSf);
        const float ltc = logf(tc + EPSf);
        eE = EPSf * itc;
        const float e0 = expf(b);
        const float ef = expf(fc);
        R0 = e0 * itc; R1 = R0 * ef; R2 = R1 * ef;
        const float fcs = fc * (1.0f / 256.0f);
        Q0s = (b - ltc) * (1.0f / 256.0f);
        Q1s = Q0s + fcs;
        Q2s = Q1s + fcs;
    }
    __syncthreads();  // LF + slib ready

    // Build per-thread half table (transposed writes, conflict-free)
    float* Ft = Fh + tid;
    {
        float cum = 0.f, x = tc;
#pragma unroll 5
        for (int n = 0; n < 100; n += 2) {
            Ft[(n >> 1) * TPB] = LF[n] - cum;
            cum += __logf(x) + __logf(x + 1.0f);
            x += 2.0f;
        }
    }
    const char* Ftb = (const char*)(Fh + tid);   // byte base for v8 addressing

    const uint32_t* gpackp = g_gpack + vgs;
    const uint2*    obsp   = (const uint2*)(g_obsT + (c * GLn + lg) * Dn);
    float* outp = out + c * VGn + vg;

#define LN2_256 (0.6931471805599453f / 256.0f)

#define BODY(k, w, dk)                                                        \
    {                                                                         \
        const uint32_t v8 = __byte_perm((w), 0, 0x4404u | (((k) & 3) << 4));  \
        const int gv = (pack >> (2 * (k))) & 3;                               \
        const float vf256 = (float)v8;           /* 256*v, exact */           \
        const float R = (gv == 0) ? R0 : ((gv == 1) ? R1 : R2);               \
        const float Qs = (gv == 0) ? Q0s : ((gv == 1) ? Q1s : Q2s);           \
        const float2 lv = slib[(dk)];                                         \
        const float r = fmaf(R, lv.x, eE);                                    \
        const float l2 = __log2f(1.0f + r);                                   \
        const float A = fmaf(vf256, LN2_256, tcln2);                          \
        float fv = *(const float*)(Ftb + (v8 & 0xFFFFFEFFu));                 \
        if (v8 & 0x100u) {                                                    \
            const float tv = vf256 + tcm;                                     \
            fv += LN2f * (__log2f(vf256) - __log2f(tv));                      \
        }                                                                     \
        const float q = Qs + lv.y;               /* already /256 */           \
        float res = fmaf(-vf256, q, fv);                                      \
        res = fmaf(A, l2, res);                                               \
        if (active) __stcs(op + (k) * (Cn * VGn), res);                       \
    }

    for (int t = 0; t < 12; t++) {
        const uint32_t pack = gpackp[t * VGn];
        const uint2 a = obsp[2 * t];
        const uint2 b = obsp[2 * t + 1];
        float* op = outp + t * 16 * (Cn * VGn);
#pragma unroll
        for (int k = 0; k < 16; k++) {
            const uint32_t w = (k < 8) ? ((k < 4) ? a.x : a.y)
                                       : ((k < 12) ? b.x : b.y);
            BODY(k, w, t * 16 + k)
        }
    }
    {   // tail: d = 192..199
        const uint32_t pack = gpackp[12 * VGn];
        const uint2 a = obsp[24];
        float* op = outp + 192 * (Cn * VGn);
#pragma unroll
        for (int k = 0; k < 8; k++) {
            const uint32_t w = (k < 4) ? a.x : a.y;
            BODY(k, w, 192 + k)
        }
    }
#undef BODY
}

// ---------------------------------------------------------------------------
extern "C" void kernel_launch(void* const* d_in, const int* in_sizes, int n_in,
                              void* d_out, int out_size) {
    const float* genotypes = nullptr;
    const float* obs       = nullptr;
    const float* fc_log    = nullptr;
    const float* lib       = nullptr;
    const float* cg[2]     = {nullptr, nullptr};
    const int*   vgarr[3]  = {nullptr, nullptr, nullptr};
    int n_cg = 0, n_vg = 0;

    for (int i = 0; i < n_in; i++) {
        switch (in_sizes[i]) {
            case Dn * Vn:        genotypes = (const float*)d_in[i]; break;
            case Dn * Cn * GLn:  obs       = (const float*)d_in[i]; break;
            case Cn * VGn:       fc_log    = (const float*)d_in[i]; break;
            case Dn * Cn:        lib       = (const float*)d_in[i]; break;
            case Cn * Gn:        if (n_cg < 2) cg[n_cg++] = (const float*)d_in[i]; break;
            case VGn:            if (n_vg < 3) vgarr[n_vg++] = (const int*)d_in[i]; break;
            default: break;
        }
    }
    const float* baseline_log   = cg[0];
    const float* dispersion_log = cg[1];
    float* out = (float*)d_out;

    classify_kernel<<<64, 256>>>(vgarr[0], vgarr[1], vgarr[2]);
    resolve_kernel<<<1, 1>>>(vgarr[0], vgarr[1], vgarr[2]);
    prep_kernel<<<(Dn * Vn / 4 + 255) / 256, 256>>>(genotypes, obs, lib);
    gsel_kernel<<<Dn, 1024>>>();
    pack_kernel<<<(VGn / 4 + 255) / 256, 256>>>();

    dim3 grid((VGn + TPB - 1) / TPB, Cn);
    main_kernel<<<grid, TPB>>>(fc_log, baseline_log, dispersion_log, out);
}

// round 14
// speedup vs baseline: 1.2294x; 1.1084x over previous
#include <cuda_runtime.h>
#include <cstdint>

#define Dn  200
#define Cn  8
#define Gn  10000
#define Vn  20000
#define VGn 50000
#define GLn 500
#define EPSf 1e-8f
#define LN2f 0.6931471805599453f

// Scratch (no allocations allowed)
__device__ __align__(16) uint8_t g_gen8[Dn * Vn];       // genotypes u8 [d][v]
__device__ __align__(16) uint8_t g_obsT[Cn * GLn * Dn]; // obs u8 TRANSPOSED [c][lg][d]
__device__ __align__(16) uint8_t g_gsel[Dn * VGn];      // genotypes[:, sel[vg]] [d][vg]
__device__ __align__(16) uint32_t g_gpack[13 * VGn];    // 2-bit packed gsel: [d/16][vg]
__device__ float2   g_lib2[Cn * Dn];                    // [c][d] = {lib, log(lib)/256}

// classification state (zero-initialized at load; atomicMax idempotent across replays)
__device__ int g_max3[3];
__device__ const int* g_p_vg2g;
__device__ const int* g_p_sel;
__device__ const int* g_p_vg2lg;

// ---------------------------------------------------------------------------
__global__ void classify_kernel(const int* __restrict__ a,
                                const int* __restrict__ b,
                                const int* __restrict__ c) {
    __shared__ int sred[256];
    const int tid = threadIdx.x;
    const int* arrs[3] = {a, b, c};
    for (int j = 0; j < 3; j++) {
        int m = 0;
        for (int i = blockIdx.x * 256 + tid; i < VGn; i += gridDim.x * 256)
            m = max(m, arrs[j][i]);
        sred[tid] = m;
        __syncthreads();
        for (int s = 128; s > 0; s >>= 1) {
            if (tid < s) sred[tid] = max(sred[tid], sred[tid + s]);
            __syncthreads();
        }
        if (tid == 0) atomicMax(&g_max3[j], sred[0]);
        __syncthreads();
    }
}

__global__ void resolve_kernel(const int* a, const int* b, const int* c) {
    const int* arrs[3] = {a, b, c};
    for (int j = 0; j < 3; j++) {
        const int m = g_max3[j];
        if (m < GLn)      g_p_vg2lg = arrs[j];
        else if (m < Gn)  g_p_vg2g  = arrs[j];
        else              g_p_sel   = arrs[j];
    }
}

// ---------------------------------------------------------------------------
__global__ void prep_kernel(const float* __restrict__ genotypes,
                            const float* __restrict__ obs,
                            const float* __restrict__ lib) {
    const int q = blockIdx.x * blockDim.x + threadIdx.x;
    if (q < Dn * Vn / 4) {
        const float4 g4 = ((const float4*)genotypes)[q];
        uint32_t w = (uint32_t)__float2int_rn(g4.x)
                   | ((uint32_t)__float2int_rn(g4.y) << 8)
                   | ((uint32_t)__float2int_rn(g4.z) << 16)
                   | ((uint32_t)__float2int_rn(g4.w) << 24);
        ((uint32_t*)g_gen8)[q] = w;
    }
    if (q < Dn * Cn * GLn / 4) {
        const float4 o4 = ((const float4*)obs)[q];
        const int i = q * 4;                    // flat [d][c][lg], GLn%4==0
        const int d  = i / (Cn * GLn);
        const int r  = i - d * (Cn * GLn);
        const int c  = r / GLn;
        const int lg = r - c * GLn;
        uint8_t* base = g_obsT + d;
        base[(c * GLn + lg + 0) * Dn] = (uint8_t)__float2int_rn(o4.x);
        base[(c * GLn + lg + 1) * Dn] = (uint8_t)__float2int_rn(o4.y);
        base[(c * GLn + lg + 2) * Dn] = (uint8_t)__float2int_rn(o4.z);
        base[(c * GLn + lg + 3) * Dn] = (uint8_t)__float2int_rn(o4.w);
    }
    if (q < Dn * Cn) {
        const int d = q / Cn;
        const int c = q - d * Cn;
        const float lv = lib[q];
        g_lib2[c * Dn + d] = make_float2(lv, logf(lv) * (1.0f / 256.0f));
    }
}

// ---------------------------------------------------------------------------
// Gather genotypes[d, sel[vg]] -> g_gsel[d, vg] (shared-staged row, 32 warps).
// 2-iteration manual batching for MLP on the sel loads.
// ---------------------------------------------------------------------------
__global__ __launch_bounds__(1024) void gsel_kernel() {
    __shared__ uint32_t row32[Vn / 4];
    const int* sel = g_p_sel;
    const int d = blockIdx.x;
    const uint32_t* src = (const uint32_t*)(g_gen8 + d * Vn);
    for (int j = threadIdx.x; j < Vn / 4; j += 1024) row32[j] = src[j];
    __syncthreads();
    const uint8_t* row = (const uint8_t*)row32;
    uint32_t* dst = (uint32_t*)(g_gsel + d * VGn);
    const int NQ = VGn / 4;            // 12500
    // batched pairs: q and q+1024
    for (int q = threadIdx.x; q + 1024 < NQ; q += 2048) {
        const int4 sA = ((const int4*)sel)[q];
        const int4 sB = ((const int4*)sel)[q + 1024];
        uint32_t wA = (uint32_t)row[sA.x]
                    | ((uint32_t)row[sA.y] << 8)
                    | ((uint32_t)row[sA.z] << 16)
                    | ((uint32_t)row[sA.w] << 24);
        uint32_t wB = (uint32_t)row[sB.x]
                    | ((uint32_t)row[sB.y] << 8)
                    | ((uint32_t)row[sB.z] << 16)
                    | ((uint32_t)row[sB.w] << 24);
        dst[q] = wA;
        dst[q + 1024] = wB;
    }
    // remainder (NQ = 12500 = 6*2048 + 212): q in [12288, 12500)
    {
        const int q = 12288 + threadIdx.x;
        if (q < NQ) {
            const int4 s4 = ((const int4*)sel)[q];
            dst[q] = (uint32_t)row[s4.x]
                   | ((uint32_t)row[s4.y] << 8)
                   | ((uint32_t)row[s4.z] << 16)
                   | ((uint32_t)row[s4.w] << 24);
        }
    }
}

// ---------------------------------------------------------------------------
__global__ void pack_kernel() {
    const int q = blockIdx.x * 256 + threadIdx.x;   // vg quad
    if (q >= VGn / 4) return;
    for (int t = 0; t < 13; t++) {
        uint32_t p0 = 0, p1 = 0, p2 = 0, p3 = 0;
        const int dmax = (t == 12) ? 8 : 16;
#pragma unroll
        for (int k = 0; k < 16; k++) {
            if (k < dmax) {
                const uint32_t w = ((const uint32_t*)(g_gsel + (t * 16 + k) * VGn))[q];
                p0 |= ((w >> 0)  & 3u) << (2 * k);
                p1 |= ((w >> 8)  & 3u) << (2 * k);
                p2 |= ((w >> 16) & 3u) << (2 * k);
                p3 |= ((w >> 24) & 3u) << (2 * k);
            }
        }
        uint32_t* dst = g_gpack + t * VGn + q * 4;
        dst[0] = p0; dst[1] = p1; dst[2] = p2; dst[3] = p3;
    }
}

// ---------------------------------------------------------------------------
// Main kernel — R13 math + per-thread RQ lookup table replacing select chains.
//   RQ[gv][tid] = float2{ R_gv, Q_gv/256 }  (thread-striped, conflict-free;
//   per-thread region only -> no cross-thread sync needed).
//   Lookup addr offset = gv * (TPB*8), gv extracted from pack.
// Rest identical to R13 (v8 PRMT trick, /256 folding, half table + odd fixup).
// ---------------------------------------------------------------------------
#define TPB 128
#define NH  50

__global__ __launch_bounds__(TPB) void main_kernel(
    const float* __restrict__ fc_log,
    const float* __restrict__ baseline_log,
    const float* __restrict__ dispersion_log,
    float*       __restrict__ out) {
    __shared__ float  LF[100];
    __shared__ float  Fh[NH * TPB];     // transposed half table, 25.6 KB
    __shared__ float2 sRQ[3 * TPB];     // RQ[gv][tid], 3 KB
    __shared__ float2 slib[Dn];

    const int tid = threadIdx.x;
    const int c   = blockIdx.y;
    const int vg  = blockIdx.x * TPB + tid;
    const bool active = (vg < VGn);
    const int vgs = active ? vg : 0;

    for (int n = tid; n < 100; n += TPB) LF[n] = lgammaf((float)(n + 1));
    for (int n = tid; n < Dn;  n += TPB) slib[n] = g_lib2[c * Dn + n];

    // Per-(c,vg) parameters
    float tc = 1.f, eE = 0.f, tcln2 = 0.f, tcm = 0.f;
    int lg = 0;
    {
        const int gix = g_p_vg2g[vgs];
        lg = g_p_vg2lg[vgs];
        const float fc = fc_log[c * VGn + vgs];
        const float b  = baseline_log[c * Gn + gix];
        const float dl = dispersion_log[c * Gn + gix];
        const float disp = fminf(expf(dl), 20.0f);
        tc = 1.0f / disp;
        tcln2 = tc * LN2f;
        tcm   = 256.0f * tc - 256.0f;          // 256*(tc-1)
        const float itc = 1.0f / (tc + EPSf);
        const float ltc = logf(tc + EPSf);
        eE = EPSf * itc;
        const float e0 = expf(b);
        const float ef = expf(fc);
        const float R0 = e0 * itc, R1 = R0 * ef, R2 = R1 * ef;
        const float fcs = fc * (1.0f / 256.0f);
        const float Q0s = (b - ltc) * (1.0f / 256.0f);
        sRQ[0 * TPB + tid] = make_float2(R0, Q0s);
        sRQ[1 * TPB + tid] = make_float2(R1, Q0s + fcs);
        sRQ[2 * TPB + tid] = make_float2(R2, Q0s + 2.0f * fcs);
    }
    __syncthreads();  // LF + slib ready (sRQ is per-thread, no sharing)

    // Build per-thread half table (transposed writes, conflict-free)
    float* Ft = Fh + tid;
    {
        float cum = 0.f, x = tc;
#pragma unroll 5
        for (int n = 0; n < 100; n += 2) {
            Ft[(n >> 1) * TPB] = LF[n] - cum;
            cum += __logf(x) + __logf(x + 1.0f);
            x += 2.0f;
        }
    }
    const char* Ftb  = (const char*)(Fh + tid);    // byte base for v8 addressing
    const char* RQb  = (const char*)(sRQ + tid);   // byte base; gv entry stride = TPB*8

    const uint32_t* gpackp = g_gpack + vgs;
    const uint2*    obsp   = (const uint2*)(g_obsT + (c * GLn + lg) * Dn);
    float* outp = out + c * VGn + vg;

#define LN2_256 (0.6931471805599453f / 256.0f)

#define BODY(k, w, dk)                                                        \
    {                                                                         \
        const uint32_t v8 = __byte_perm((w), 0, 0x4404u | (((k) & 3) << 4));  \
        const uint32_t gvoff = ((pack >> (2 * (k))) & 3u) * (TPB * 8u);       \
        const float2 RQ = *(const float2*)(RQb + gvoff);                      \
        const float vf256 = (float)v8;           /* 256*v, exact */           \
        const float2 lv = slib[(dk)];                                         \
        const float r = fmaf(RQ.x, lv.x, eE);                                 \
        const float l2 = __log2f(1.0f + r);                                   \
        const float A = fmaf(vf256, LN2_256, tcln2);                          \
        float fv = *(const float*)(Ftb + (v8 & 0xFFFFFEFFu));                 \
        if (v8 & 0x100u) {                                                    \
            const float tv = vf256 + tcm;                                     \
            fv += LN2f * (__log2f(vf256) - __log2f(tv));                      \
        }                                                                     \
        const float q = RQ.y + lv.y;             /* both already /256 */      \
        float res = fmaf(-vf256, q, fv);                                      \
        res = fmaf(A, l2, res);                                               \
        if (active) __stcs(op + (k) * (Cn * VGn), res);                       \
    }

    for (int t = 0; t < 12; t++) {
        const uint32_t pack = gpackp[t * VGn];
        const uint2 a = obsp[2 * t];
        const uint2 b = obsp[2 * t + 1];
        float* op = outp + t * 16 * (Cn * VGn);
#pragma unroll
        for (int k = 0; k < 16; k++) {
            const uint32_t w = (k < 8) ? ((k < 4) ? a.x : a.y)
                                       : ((k < 12) ? b.x : b.y);
            BODY(k, w, t * 16 + k)
        }
    }
    {   // tail: d = 192..199
        const uint32_t pack = gpackp[12 * VGn];
        const uint2 a = obsp[24];
        float* op = outp + 192 * (Cn * VGn);
#pragma unroll
        for (int k = 0; k < 8; k++) {
            const uint32_t w = (k < 4) ? a.x : a.y;
            BODY(k, w, 192 + k)
        }
    }
#undef BODY
}

// ---------------------------------------------------------------------------
extern "C" void kernel_launch(void* const* d_in, const int* in_sizes, int n_in,
                              void* d_out, int out_size) {
    const float* genotypes = nullptr;
    const float* obs       = nullptr;
    const float* fc_log    = nullptr;
    const float* lib       = nullptr;
    const float* cg[2]     = {nullptr, nullptr};
    const int*   vgarr[3]  = {nullptr, nullptr, nullptr};
    int n_cg = 0, n_vg = 0;

    for (int i = 0; i < n_in; i++) {
        switch (in_sizes[i]) {
            case Dn * Vn:        genotypes = (const float*)d_in[i]; break;
            case Dn * Cn * GLn:  obs       = (const float*)d_in[i]; break;
            case Cn * VGn:       fc_log    = (const float*)d_in[i]; break;
            case Dn * Cn:        lib       = (const float*)d_in[i]; break;
            case Cn * Gn:        if (n_cg < 2) cg[n_cg++] = (const float*)d_in[i]; break;
            case VGn:            if (n_vg < 3) vgarr[n_vg++] = (const int*)d_in[i]; break;
            default: break;
        }
    }
    const float* baseline_log   = cg[0];
    const float* dispersion_log = cg[1];
    float* out = (float*)d_out;

    classify_kernel<<<64, 256>>>(vgarr[0], vgarr[1], vgarr[2]);
    resolve_kernel<<<1, 1>>>(vgarr[0], vgarr[1], vgarr[2]);
    prep_kernel<<<(Dn * Vn / 4 + 255) / 256, 256>>>(genotypes, obs, lib);
    gsel_kernel<<<Dn, 1024>>>();
    pack_kernel<<<(VGn / 4 + 255) / 256, 256>>>();

    dim3 grid((VGn + TPB - 1) / TPB, Cn);
    main_kernel<<<grid, TPB>>>(fc_log, baseline_log, dispersion_log, out);
}

// round 16
// speedup vs baseline: 1.3942x; 1.1340x over previous
#include <cuda_runtime.h>
#include <cstdint>

#define Dn  200
#define Cn  8
#define Gn  10000
#define Vn  20000
#define VGn 50000
#define GLn 500
#define EPSf 1e-8f
#define LN2f 0.6931471805599453f

#define V16 (Vn / 16)      // 1250 u32 per 2-bit packed genotype row
#define NDG 13             // d-groups of 16 (last has 8 real rows)

// Scratch (no allocations allowed)
__device__ __align__(16) uint32_t g_gen2[(NDG * 16) * V16]; // 2-bit genotypes [d][w]; rows >=Dn stay 0
__device__ __align__(16) uint8_t  g_obsT[Cn * GLn * Dn];    // obs u8 TRANSPOSED [c][lg][d]
__device__ __align__(16) uint32_t g_gpack[NDG * VGn];       // 2-bit packed gsel: [d/16][vg]
__device__ float2   g_lib2[Cn * Dn];                        // [c][d] = {lib, log(lib)/256}

// classification state (zero-initialized at load; atomicMax idempotent across replays)
__device__ int g_max3[3];
__device__ const int* g_p_vg2g;
__device__ const int* g_p_sel;
__device__ const int* g_p_vg2lg;

// ---------------------------------------------------------------------------
__global__ void classify_kernel(const int* __restrict__ a,
                                const int* __restrict__ b,
                                const int* __restrict__ c) {
    __shared__ int sred[256];
    const int tid = threadIdx.x;
    const int* arrs[3] = {a, b, c};
    for (int j = 0; j < 3; j++) {
        int m = 0;
        for (int i = blockIdx.x * 256 + tid; i < VGn; i += gridDim.x * 256)
            m = max(m, arrs[j][i]);
        sred[tid] = m;
        __syncthreads();
        for (int s = 128; s > 0; s >>= 1) {
            if (tid < s) sred[tid] = max(sred[tid], sred[tid + s]);
            __syncthreads();
        }
        if (tid == 0) atomicMax(&g_max3[j], sred[0]);
        __syncthreads();
    }
}

__global__ void resolve_kernel(const int* a, const int* b, const int* c) {
    const int* arrs[3] = {a, b, c};
    for (int j = 0; j < 3; j++) {
        const int m = g_max3[j];
        if (m < GLn)      g_p_vg2lg = arrs[j];
        else if (m < Gn)  g_p_vg2g  = arrs[j];
        else              g_p_sel   = arrs[j];
    }
}

// ---------------------------------------------------------------------------
// Prep: genotypes -> 2-bit packed rows; obs -> u8 transposed; lib -> {lib, log/256}
// Grid MUST cover Dn*V16 = 250,000 threads (largest extent).
// ---------------------------------------------------------------------------
__global__ void prep_kernel(const float* __restrict__ genotypes,
                            const float* __restrict__ obs,
                            const float* __restrict__ lib) {
    const int q = blockIdx.x * blockDim.x + threadIdx.x;
    if (q < Dn * V16) {                    // one u32 (16 genotypes) per thread
        const int d  = q / V16;
        const int w  = q - d * V16;
        const float4* src = (const float4*)(genotypes + d * Vn + w * 16);
        uint32_t p = 0;
#pragma unroll
        for (int j = 0; j < 4; j++) {
            const float4 g4 = src[j];
            p |= ((uint32_t)__float2int_rn(g4.x) & 3u) << (8 * j + 0);
            p |= ((uint32_t)__float2int_rn(g4.y) & 3u) << (8 * j + 2);
            p |= ((uint32_t)__float2int_rn(g4.z) & 3u) << (8 * j + 4);
            p |= ((uint32_t)__float2int_rn(g4.w) & 3u) << (8 * j + 6);
        }
        g_gen2[d * V16 + w] = p;
    }
    if (q < Dn * Cn * GLn / 4) {
        const float4 o4 = ((const float4*)obs)[q];
        const int i = q * 4;                    // flat [d][c][lg], GLn%4==0
        const int d  = i / (Cn * GLn);
        const int r  = i - d * (Cn * GLn);
        const int c  = r / GLn;
        const int lg = r - c * GLn;
        uint8_t* base = g_obsT + d;
        base[(c * GLn + lg + 0) * Dn] = (uint8_t)__float2int_rn(o4.x);
        base[(c * GLn + lg + 1) * Dn] = (uint8_t)__float2int_rn(o4.y);
        base[(c * GLn + lg + 2) * Dn] = (uint8_t)__float2int_rn(o4.z);
        base[(c * GLn + lg + 3) * Dn] = (uint8_t)__float2int_rn(o4.w);
    }
    if (q < Dn * Cn) {
        const int d = q / Cn;
        const int c = q - d * Cn;
        const float lv = lib[q];
        g_lib2[c * Dn + d] = make_float2(lv, logf(lv) * (1.0f / 256.0f));
    }
}

// ---------------------------------------------------------------------------
// Fused gather+pack: block (t, chunk) stages 16 packed genotype rows (80 KB
// dynamic smem), then per vg: sel lookup -> 16 2-bit extracts -> g_gpack[t][vg].
// Rows beyond Dn are zero in g_gen2, so the tail d-group needs no branches.
// ---------------------------------------------------------------------------
#define GP_TPB 1024
#define GP_CHUNKS 12

__global__ __launch_bounds__(GP_TPB) void gselpack_kernel() {
    extern __shared__ uint32_t rows2[];     // [16][V16] = 80000 B
    const int t  = blockIdx.x;              // d-group
    const int d0 = t * 16;
    for (int i = threadIdx.x; i < 16 * V16; i += GP_TPB)
        rows2[i] = g_gen2[d0 * V16 + i];
    __syncthreads();
    const int* sel = g_p_sel;
    const int chunk  = (VGn + GP_CHUNKS - 1) / GP_CHUNKS;
    const int vstart = blockIdx.y * chunk;
    const int vend   = min(vstart + chunk, VGn);
    uint32_t* dst = g_gpack + t * VGn;
    for (int vg = vstart + threadIdx.x; vg < vend; vg += GP_TPB) {
        const int s  = sel[vg];
        const int w  = s >> 4;
        const int sh = (s & 15) * 2;
        uint32_t p = 0;
#pragma unroll
        for (int dr = 0; dr < 16; dr++)
            p |= ((rows2[dr * V16 + w] >> sh) & 3u) << (2 * dr);
        dst[vg] = p;
    }
}

// ---------------------------------------------------------------------------
// Main kernel — unchanged from R14 (measured best).
// ---------------------------------------------------------------------------
#define TPB 128
#define NH  50

__global__ __launch_bounds__(TPB) void main_kernel(
    const float* __restrict__ fc_log,
    const float* __restrict__ baseline_log,
    const float* __restrict__ dispersion_log,
    float*       __restrict__ out) {
    __shared__ float  LF[100];
    __shared__ float  Fh[NH * TPB];     // transposed half table, 25.6 KB
    __shared__ float2 sRQ[3 * TPB];     // RQ[gv][tid], 3 KB
    __shared__ float2 slib[Dn];

    const int tid = threadIdx.x;
    const int c   = blockIdx.y;
    const int vg  = blockIdx.x * TPB + tid;
    const bool active = (vg < VGn);
    const int vgs = active ? vg : 0;

    for (int n = tid; n < 100; n += TPB) LF[n] = lgammaf((float)(n + 1));
    for (int n = tid; n < Dn;  n += TPB) slib[n] = g_lib2[c * Dn + n];

    // Per-(c,vg) parameters
    float tc = 1.f, eE = 0.f, tcln2 = 0.f, tcm = 0.f;
    int lg = 0;
    {
        const int gix = g_p_vg2g[vgs];
        lg = g_p_vg2lg[vgs];
        const float fc = fc_log[c * VGn + vgs];
        const float b  = baseline_log[c * Gn + gix];
        const float dl = dispersion_log[c * Gn + gix];
        const float disp = fminf(expf(dl), 20.0f);
        tc = 1.0f / disp;
        tcln2 = tc * LN2f;
        tcm   = 256.0f * tc - 256.0f;          // 256*(tc-1)
        const float itc = 1.0f / (tc + EPSf);
        const float ltc = logf(tc + EPSf);
        eE = EPSf * itc;
        const float e0 = expf(b);
        const float ef = expf(fc);
        const float R0 = e0 * itc, R1 = R0 * ef, R2 = R1 * ef;
        const float fcs = fc * (1.0f / 256.0f);
        const float Q0s = (b - ltc) * (1.0f / 256.0f);
        sRQ[0 * TPB + tid] = make_float2(R0, Q0s);
        sRQ[1 * TPB + tid] = make_float2(R1, Q0s + fcs);
        sRQ[2 * TPB + tid] = make_float2(R2, Q0s + 2.0f * fcs);
    }
    __syncthreads();  // LF + slib ready (sRQ per-thread)

    // Build per-thread half table (transposed writes, conflict-free)
    float* Ft = Fh + tid;
    {
        float cum = 0.f, x = tc;
#pragma unroll 5
        for (int n = 0; n < 100; n += 2) {
            Ft[(n >> 1) * TPB] = LF[n] - cum;
            cum += __logf(x) + __logf(x + 1.0f);
            x += 2.0f;
        }
    }
    const char* Ftb  = (const char*)(Fh + tid);
    const char* RQb  = (const char*)(sRQ + tid);

    const uint32_t* gpackp = g_gpack + vgs;
    const uint2*    obsp   = (const uint2*)(g_obsT + (c * GLn + lg) * Dn);
    float* outp = out + c * VGn + vg;

#define LN2_256 (0.6931471805599453f / 256.0f)

#define BODY(k, w, dk)                                                        \
    {                                                                         \
        const uint32_t v8 = __byte_perm((w), 0, 0x4404u | (((k) & 3) << 4));  \
        const uint32_t gvoff = ((pack >> (2 * (k))) & 3u) * (TPB * 8u);       \
        const float2 RQ = *(const float2*)(RQb + gvoff);                      \
        const float vf256 = (float)v8;           /* 256*v, exact */           \
        const float2 lv = slib[(dk)];                                         \
        const float r = fmaf(RQ.x, lv.x, eE);                                 \
        const float l2 = __log2f(1.0f + r);                                   \
        const float A = fmaf(vf256, LN2_256, tcln2);                          \
        float fv = *(const float*)(Ftb + (v8 & 0xFFFFFEFFu));                 \
        if (v8 & 0x100u) {                                                    \
            const float tv = vf256 + tcm;                                     \
            fv += LN2f * (__log2f(vf256) - __log2f(tv));                      \
        }                                                                     \
        const float q = RQ.y + lv.y;             /* both already /256 */      \
        float res = fmaf(-vf256, q, fv);                                      \
        res = fmaf(A, l2, res);                                               \
        if (active) __stcs(op + (k) * (Cn * VGn), res);                       \
    }

    for (int t = 0; t < 12; t++) {
        const uint32_t pack = gpackp[t * VGn];
        const uint2 a = obsp[2 * t];
        const uint2 b = obsp[2 * t + 1];
        float* op = outp + t * 16 * (Cn * VGn);
#pragma unroll
        for (int k = 0; k < 16; k++) {
            const uint32_t w = (k < 8) ? ((k < 4) ? a.x : a.y)
                                       : ((k < 12) ? b.x : b.y);
            BODY(k, w, t * 16 + k)
        }
    }
    {   // tail: d = 192..199
        const uint32_t pack = gpackp[12 * VGn];
        const uint2 a = obsp[24];
        float* op = outp + 192 * (Cn * VGn);
#pragma unroll
        for (int k = 0; k < 8; k++) {
            const uint32_t w = (k < 4) ? a.x : a.y;
            BODY(k, w, 192 + k)
        }
    }
#undef BODY
}

// ---------------------------------------------------------------------------
extern "C" void kernel_launch(void* const* d_in, const int* in_sizes, int n_in,
                              void* d_out, int out_size) {
    const float* genotypes = nullptr;
    const float* obs       = nullptr;
    const float* fc_log    = nullptr;
    const float* lib       = nullptr;
    const float* cg[2]     = {nullptr, nullptr};
    const int*   vgarr[3]  = {nullptr, nullptr, nullptr};
    int n_cg = 0, n_vg = 0;

    for (int i = 0; i < n_in; i++) {
        switch (in_sizes[i]) {
            case Dn * Vn:        genotypes = (const float*)d_in[i]; break;
            case Dn * Cn * GLn:  obs       = (const float*)d_in[i]; break;
            case Cn * VGn:       fc_log    = (const float*)d_in[i]; break;
            case Dn * Cn:        lib       = (const float*)d_in[i]; break;
            case Cn * Gn:        if (n_cg < 2) cg[n_cg++] = (const float*)d_in[i]; break;
            case VGn:            if (n_vg < 3) vgarr[n_vg++] = (const int*)d_in[i]; break;
            default: break;
        }
    }
    const float* baseline_log   = cg[0];
    const float* dispersion_log = cg[1];
    float* out = (float*)d_out;

    // 80 KB dynamic smem for the fused gather+pack (host-side attr, capture-safe)
    static const int GP_SMEM = 16 * V16 * 4;
    cudaFuncSetAttribute(gselpack_kernel,
                         cudaFuncAttributeMaxDynamicSharedMemorySize, GP_SMEM);

    classify_kernel<<<64, 256>>>(vgarr[0], vgarr[1], vgarr[2]);
    resolve_kernel<<<1, 1>>>(vgarr[0], vgarr[1], vgarr[2]);
    // FIX: grid must cover Dn*V16 = 250,000 genotype-pack threads (was 200,000)
    prep_kernel<<<(Dn * V16 + 255) / 256, 256>>>(genotypes, obs, lib);
    dim3 gpgrid(NDG, GP_CHUNKS);
    gselpack_kernel<<<gpgrid, GP_TPB, GP_SMEM>>>();

    dim3 grid((VGn + TPB - 1) / TPB, Cn);
    main_kernel<<<grid, TPB>>>(fc_log, baseline_log, dispersion_log, out);
}

// round 17
// speedup vs baseline: 1.3974x; 1.0024x over previous
#include <cuda_runtime.h>
#include <cstdint>

#define Dn  200
#define Cn  8
#define Gn  10000
#define Vn  20000
#define VGn 50000
#define GLn 500
#define EPSf 1e-8f
#define LN2f 0.6931471805599453f

#define V16 (Vn / 16)      // 1250 u32 per 2-bit packed genotype row
#define NDG 13             // d-groups of 16 (last has 8 real rows)
#define GTS 16             // g_genT row stride in words (64B, uint4-aligned)

// Scratch (no allocations allowed)
__device__ __align__(16) uint32_t g_gen2[(NDG * 16) * V16]; // 2-bit genotypes [d][w]; rows >=Dn stay 0
__device__ __align__(16) uint32_t g_genT[Vn * GTS];         // transposed: [v][t] (16 d per word)
__device__ __align__(16) uint8_t  g_obsT[Cn * GLn * Dn];    // obs u8 TRANSPOSED [c][lg][d]
__device__ __align__(16) uint32_t g_gpack[NDG * VGn];       // 2-bit packed gsel: [d/16][vg]
__device__ float2   g_lib2[Cn * Dn];                        // [c][d] = {lib, log(lib)/256}

// classification state (zero-initialized at load; atomicMax idempotent across replays)
__device__ int g_max3[3];
__device__ const int* g_p_vg2g;
__device__ const int* g_p_sel;
__device__ const int* g_p_vg2lg;

// ---------------------------------------------------------------------------
__global__ void classify_kernel(const int* __restrict__ a,
                                const int* __restrict__ b,
                                const int* __restrict__ c) {
    __shared__ int sred[256];
    const int tid = threadIdx.x;
    const int* arrs[3] = {a, b, c};
    for (int j = 0; j < 3; j++) {
        int m = 0;
        for (int i = blockIdx.x * 256 + tid; i < VGn; i += gridDim.x * 256)
            m = max(m, arrs[j][i]);
        sred[tid] = m;
        __syncthreads();
        for (int s = 128; s > 0; s >>= 1) {
            if (tid < s) sred[tid] = max(sred[tid], sred[tid + s]);
            __syncthreads();
        }
        if (tid == 0) atomicMax(&g_max3[j], sred[0]);
        __syncthreads();
    }
}

__global__ void resolve_kernel(const int* a, const int* b, const int* c) {
    const int* arrs[3] = {a, b, c};
    for (int j = 0; j < 3; j++) {
        const int m = g_max3[j];
        if (m < GLn)      g_p_vg2lg = arrs[j];
        else if (m < Gn)  g_p_vg2g  = arrs[j];
        else              g_p_sel   = arrs[j];
    }
}

// ---------------------------------------------------------------------------
// Prep: genotypes -> 2-bit packed rows; obs -> u8 transposed; lib -> {lib, log/256}
// Grid covers Dn*V16 = 250,000 threads (largest extent).
// ---------------------------------------------------------------------------
__global__ void prep_kernel(const float* __restrict__ genotypes,
                            const float* __restrict__ obs,
                            const float* __restrict__ lib) {
    const int q = blockIdx.x * blockDim.x + threadIdx.x;
    if (q < Dn * V16) {                    // one u32 (16 genotypes) per thread
        const int d  = q / V16;
        const int w  = q - d * V16;
        const float4* src = (const float4*)(genotypes + d * Vn + w * 16);
        uint32_t p = 0;
#pragma unroll
        for (int j = 0; j < 4; j++) {
            const float4 g4 = src[j];
            p |= ((uint32_t)__float2int_rn(g4.x) & 3u) << (8 * j + 0);
            p |= ((uint32_t)__float2int_rn(g4.y) & 3u) << (8 * j + 2);
            p |= ((uint32_t)__float2int_rn(g4.z) & 3u) << (8 * j + 4);
            p |= ((uint32_t)__float2int_rn(g4.w) & 3u) << (8 * j + 6);
        }
        g_gen2[d * V16 + w] = p;
    }
    if (q < Dn * Cn * GLn / 4) {
        const float4 o4 = ((const float4*)obs)[q];
        const int i = q * 4;                    // flat [d][c][lg], GLn%4==0
        const int d  = i / (Cn * GLn);
        const int r  = i - d * (Cn * GLn);
        const int c  = r / GLn;
        const int lg = r - c * GLn;
        uint8_t* base = g_obsT + d;
        base[(c * GLn + lg + 0) * Dn] = (uint8_t)__float2int_rn(o4.x);
        base[(c * GLn + lg + 1) * Dn] = (uint8_t)__float2int_rn(o4.y);
        base[(c * GLn + lg + 2) * Dn] = (uint8_t)__float2int_rn(o4.z);
        base[(c * GLn + lg + 3) * Dn] = (uint8_t)__float2int_rn(o4.w);
    }
    if (q < Dn * Cn) {
        const int d = q / Cn;
        const int c = q - d * Cn;
        const float lv = lib[q];
        g_lib2[c * Dn + d] = make_float2(lv, logf(lv) * (1.0f / 256.0f));
    }
}

// ---------------------------------------------------------------------------
// Transpose 2-bit genotypes: g_gen2[d][w] -> g_genT[v][t] (16 d's per word).
// Thread (t, w): coalesced LDG of column w over 16 rows, 16x16 2-bit register
// transpose, write 16 output words. Rows >= Dn are zero -> tail t handled free.
// ---------------------------------------------------------------------------
__global__ void gent_kernel() {
    const int idx = blockIdx.x * 256 + threadIdx.x;   // t*V16 + w
    if (idx >= NDG * V16) return;
    const int t = idx / V16;
    const int w = idx - t * V16;
    uint32_t in[16];
#pragma unroll
    for (int dr = 0; dr < 16; dr++)
        in[dr] = g_gen2[(t * 16 + dr) * V16 + w];
#pragma unroll
    for (int j = 0; j < 16; j++) {
        uint32_t p = 0;
#pragma unroll
        for (int dr = 0; dr < 16; dr++)
            p |= ((in[dr] >> (2 * j)) & 3u) << (2 * dr);
        g_genT[(w * 16 + j) * GTS + t] = p;
    }
}

// ---------------------------------------------------------------------------
// Gather: thread per vg. 1 sel LDG + 3 contiguous uint4 LDG (52B used of 64B
// L2-resident row) + 13 coalesced STG. No smem, no dependent chains.
// ---------------------------------------------------------------------------
__global__ void gather_kernel() {
    const int vg = blockIdx.x * 256 + threadIdx.x;
    if (vg >= VGn) return;
    const int s = g_p_sel[vg];
    const uint4* src = (const uint4*)(g_genT + s * GTS);
    const uint4 a = src[0];
    const uint4 b = src[1];
    const uint4 c = src[2];
    const uint32_t m = g_genT[s * GTS + 12];
    uint32_t* dst = g_gpack + vg;
    dst[0 * VGn] = a.x;  dst[1 * VGn] = a.y;  dst[2 * VGn]  = a.z;  dst[3 * VGn]  = a.w;
    dst[4 * VGn] = b.x;  dst[5 * VGn] = b.y;  dst[6 * VGn]  = b.z;  dst[7 * VGn]  = b.w;
    dst[8 * VGn] = c.x;  dst[9 * VGn] = c.y;  dst[10 * VGn] = c.z;  dst[11 * VGn] = c.w;
    dst[12 * VGn] = m;
}

// ---------------------------------------------------------------------------
// Main kernel — unchanged from R14/R16 (measured best).
// ---------------------------------------------------------------------------
#define TPB 128
#define NH  50

__global__ __launch_bounds__(TPB) void main_kernel(
    const float* __restrict__ fc_log,
    const float* __restrict__ baseline_log,
    const float* __restrict__ dispersion_log,
    float*       __restrict__ out) {
    __shared__ float  LF[100];
    __shared__ float  Fh[NH * TPB];     // transposed half table, 25.6 KB
    __shared__ float2 sRQ[3 * TPB];     // RQ[gv][tid], 3 KB
    __shared__ float2 slib[Dn];

    const int tid = threadIdx.x;
    const int c   = blockIdx.y;
    const int vg  = blockIdx.x * TPB + tid;
    const bool active = (vg < VGn);
    const int vgs = active ? vg : 0;

    for (int n = tid; n < 100; n += TPB) LF[n] = lgammaf((float)(n + 1));
    for (int n = tid; n < Dn;  n += TPB) slib[n] = g_lib2[c * Dn + n];

    // Per-(c,vg) parameters
    float tc = 1.f, eE = 0.f, tcln2 = 0.f, tcm = 0.f;
    int lg = 0;
    {
        const int gix = g_p_vg2g[vgs];
        lg = g_p_vg2lg[vgs];
        const float fc = fc_log[c * VGn + vgs];
        const float b  = baseline_log[c * Gn + gix];
        const float dl = dispersion_log[c * Gn + gix];
        const float disp = fminf(expf(dl), 20.0f);
        tc = 1.0f / disp;
        tcln2 = tc * LN2f;
        tcm   = 256.0f * tc - 256.0f;          // 256*(tc-1)
        const float itc = 1.0f / (tc + EPSf);
        const float ltc = logf(tc + EPSf);
        eE = EPSf * itc;
        const float e0 = expf(b);
        const float ef = expf(fc);
        const float R0 = e0 * itc, R1 = R0 * ef, R2 = R1 * ef;
        const float fcs = fc * (1.0f / 256.0f);
        const float Q0s = (b - ltc) * (1.0f / 256.0f);
        sRQ[0 * TPB + tid] = make_float2(R0, Q0s);
        sRQ[1 * TPB + tid] = make_float2(R1, Q0s + fcs);
        sRQ[2 * TPB + tid] = make_float2(R2, Q0s + 2.0f * fcs);
    }
    __syncthreads();  // LF + slib ready (sRQ per-thread)

    // Build per-thread half table (transposed writes, conflict-free)
    float* Ft = Fh + tid;
    {
        float cum = 0.f, x = tc;
#pragma unroll 5
        for (int n = 0; n < 100; n += 2) {
            Ft[(n >> 1) * TPB] = LF[n] - cum;
            cum += __logf(x) + __logf(x + 1.0f);
            x += 2.0f;
        }
    }
    const char* Ftb  = (const char*)(Fh + tid);
    const char* RQb  = (const char*)(sRQ + tid);

    const uint32_t* gpackp = g_gpack + vgs;
    const uint2*    obsp   = (const uint2*)(g_obsT + (c * GLn + lg) * Dn);
    float* outp = out + c * VGn + vg;

#define LN2_256 (0.6931471805599453f / 256.0f)

#define BODY(k, w, dk)                                                        \
    {                                                                         \
        const uint32_t v8 = __byte_perm((w), 0, 0x4404u | (((k) & 3) << 4));  \
        const uint32_t gvoff = ((pack >> (2 * (k))) & 3u) * (TPB * 8u);       \
        const float2 RQ = *(const float2*)(RQb + gvoff);                      \
        const float vf256 = (float)v8;           /* 256*v, exact */           \
        const float2 lv = slib[(dk)];                                         \
        const float r = fmaf(RQ.x, lv.x, eE);                                 \
        const float l2 = __log2f(1.0f + r);                                   \
        const float A = fmaf(vf256, LN2_256, tcln2);                          \
        float fv = *(const float*)(Ftb + (v8 & 0xFFFFFEFFu));                 \
        if (v8 & 0x100u) {                                                    \
            const float tv = vf256 + tcm;                                     \
            fv += LN2f * (__log2f(vf256) - __log2f(tv));                      \
        }                                                                     \
        const float q = RQ.y + lv.y;             /* both already /256 */      \
        float res = fmaf(-vf256, q, fv);                                      \
        res = fmaf(A, l2, res);                                               \
        if (active) __stcs(op + (k) * (Cn * VGn), res);                       \
    }

    for (int t = 0; t < 12; t++) {
        const uint32_t pack = gpackp[t * VGn];
        const uint2 a = obsp[2 * t];
        const uint2 b = obsp[2 * t + 1];
        float* op = outp + t * 16 * (Cn * VGn);
#pragma unroll
        for (int k = 0; k < 16; k++) {
            const uint32_t w = (k < 8) ? ((k < 4) ? a.x : a.y)
                                       : ((k < 12) ? b.x : b.y);
            BODY(k, w, t * 16 + k)
        }
    }
    {   // tail: d = 192..199
        const uint32_t pack = gpackp[12 * VGn];
        const uint2 a = obsp[24];
        float* op = outp + 192 * (Cn * VGn);
#pragma unroll
        for (int k = 0; k < 8; k++) {
            const uint32_t w = (k < 4) ? a.x : a.y;
            BODY(k, w, 192 + k)
        }
    }
#undef BODY
}

// ---------------------------------------------------------------------------
extern "C" void kernel_launch(void* const* d_in, const int* in_sizes, int n_in,
                              void* d_out, int out_size) {
    const float* genotypes = nullptr;
    const float* obs       = nullptr;
    const float* fc_log    = nullptr;
    const float* lib       = nullptr;
    const float* cg[2]     = {nullptr, nullptr};
    const int*   vgarr[3]  = {nullptr, nullptr, nullptr};
    int n_cg = 0, n_vg = 0;

    for (int i = 0; i < n_in; i++) {
        switch (in_sizes[i]) {
            case Dn * Vn:        genotypes = (const float*)d_in[i]; break;
            case Dn * Cn * GLn:  obs       = (const float*)d_in[i]; break;
            case Cn * VGn:       fc_log    = (const float*)d_in[i]; break;
            case Dn * Cn:        lib       = (const float*)d_in[i]; break;
            case Cn * Gn:        if (n_cg < 2) cg[n_cg++] = (const float*)d_in[i]; break;
            case VGn:            if (n_vg < 3) vgarr[n_vg++] = (const int*)d_in[i]; break;
            default: break;
        }
    }
    const float* baseline_log   = cg[0];
    const float* dispersion_log = cg[1];
    float* out = (float*)d_out;

    classify_kernel<<<64, 256>>>(vgarr[0], vgarr[1], vgarr[2]);
    resolve_kernel<<<1, 1>>>(vgarr[0], vgarr[1], vgarr[2]);
    prep_kernel<<<(Dn * V16 + 255) / 256, 256>>>(genotypes, obs, lib);
    gent_kernel<<<(NDG * V16 + 255) / 256, 256>>>();
    gather_kernel<<<(VGn + 255) / 256, 256>>>();

    dim3 grid((VGn + TPB - 1) / TPB, Cn);
    main_kernel<<<grid, TPB>>>(fc_log, baseline_log, dispersion_log, out);
}